// round 7
// baseline (speedup 1.0000x reference)
#include <cuda_runtime.h>
#include <cuda_bf16.h>

// ---------------- problem constants ----------------
#define BB   128      // windows (= batch*nW)
#define LL   256      // tokens per window
#define NHEAD 4
#define HD   32
#define NT   225      // rpe table rows

// ---------------- scratch (static device globals) ----------------
__device__ float g_qkv[BB * LL * 384];      // [b][l][384]
__device__ float g_ctx[BB * LL * 128];      // [b][l][128]
__device__ float g_wqkvT[128 * 384];        // [k][n]
__device__ float g_wprojT[128 * 128];       // [k][n]

__device__ __forceinline__ void axpy(float a, const float4 b, float4& c) {
    c.x = fmaf(a, b.x, c.x); c.y = fmaf(a, b.y, c.y);
    c.z = fmaf(a, b.z, c.z); c.w = fmaf(a, b.w, c.w);
}

// ---------------- dummy (ncu launch-index alignment) ------------
__global__ void k_dummy() {}

// ---------------- kernel 0: transpose weights ----------------
__global__ void k_transpose(const float* __restrict__ wq, const float* __restrict__ wp) {
    int e = blockIdx.x * 256 + threadIdx.x;
    if (e < 384 * 128) { int n = e >> 7, k = e & 127; g_wqkvT[k * 384 + n] = wq[e]; }
    if (e < 128 * 128) { int n = e >> 7, k = e & 127; g_wprojT[k * 128 + n] = wp[e]; }
}

// ---------------- GEMM: C[p,n] = A[p,:128] @ Bt[:128,n] + bias[n] ----------
#define GEMM_SMEM_BYTES (64 * 132 * 4 + 128 * 32 * 16)
__global__ void k_gemm(const float* __restrict__ A, const float* __restrict__ Bt,
                       const float* __restrict__ bias, float* __restrict__ C, int N) {
    extern __shared__ float sm[];
    float*  xs = sm;                          // [64][132]
    float4* ws = (float4*)(sm + 64 * 132);    // [128][32] float4

    int p0 = blockIdx.x * 64, n0 = blockIdx.y * 128;
    int tid = threadIdx.x;

    const float4* A4 = (const float4*)A;
#pragma unroll
    for (int it = 0; it < 8; ++it) {
        int e = it * 256 + tid; int r = e >> 5, k4 = e & 31;
        float4 v = A4[(p0 + r) * 32 + k4];
        *(float4*)&xs[r * 132 + k4 * 4] = v;
    }
    const float4* B4 = (const float4*)Bt; int N4 = N >> 2;
#pragma unroll
    for (int it = 0; it < 16; ++it) {
        int e = it * 256 + tid; int k = e >> 5, n4 = e & 31;
        ws[k * 32 + n4] = B4[k * N4 + (n0 >> 2) + n4];
    }
    __syncthreads();

    int tx = tid & 15, ty = tid >> 4;
    int i0 = ty * 4, eo = ty & 1;
    int jA = 2 * tx + eo, jB = 2 * tx + (1 ^ eo);

    float4 z = make_float4(0.f, 0.f, 0.f, 0.f);
    float4 aA0 = z, aA1 = z, aA2 = z, aA3 = z;
    float4 aB0 = z, aB1 = z, aB2 = z, aB3 = z;

#pragma unroll 8
    for (int k = 0; k < 128; ++k) {
        float4 bA = ws[k * 32 + jA];
        float4 bB = ws[k * 32 + jB];
        float a0 = xs[(i0 + 0) * 132 + k];
        float a1 = xs[(i0 + 1) * 132 + k];
        float a2 = xs[(i0 + 2) * 132 + k];
        float a3 = xs[(i0 + 3) * 132 + k];
        axpy(a0, bA, aA0); axpy(a1, bA, aA1); axpy(a2, bA, aA2); axpy(a3, bA, aA3);
        axpy(a0, bB, aB0); axpy(a1, bB, aB1); axpy(a2, bB, aB2); axpy(a3, bB, aB3);
    }

    int nA = n0 + jA * 4, nB = n0 + jB * 4;
    float4 bsA = *(const float4*)&bias[nA];
    float4 bsB = *(const float4*)&bias[nB];
    float4 accA[4] = {aA0, aA1, aA2, aA3};
    float4 accB[4] = {aB0, aB1, aB2, aB3};
#pragma unroll
    for (int r = 0; r < 4; ++r) {
        int row = p0 + i0 + r;
        float4 oa = accA[r]; oa.x += bsA.x; oa.y += bsA.y; oa.z += bsA.z; oa.w += bsA.w;
        float4 ob = accB[r]; ob.x += bsB.x; ob.y += bsB.y; ob.z += bsB.z; ob.w += bsB.w;
        *(float4*)&C[row * N + nA] = oa;
        *(float4*)&C[row * N + nB] = ob;
    }
}

// ---------------- fused window attention: one CTA per (b, h), 512 threads ---
// smem offsets in floats:
#define OFF_QT   0        // qT[32][260]  (scaled, c-major)
#define OFF_KT   8320     // kT[32][260]
#define OFF_V    16640    // v[256][32]
#define OFF_QR   24832    // q_rpe*scale [225][33]
#define OFF_KR   32260    // k_rpe       [225][33]
#define OFF_VR   39688    // v_rpe       [225][32]
#define OFF_SB   46888    // score/prob buffer [32][260]
#define OFF_OB   55208    // j-half partials [32][32]
#define OFF_REL  56232    // uint8 rel_idx [64*64] = 1024 floats
#define ATTN_SMEM_FLOATS (OFF_REL + 1024)
#define ATTN_SMEM_BYTES  (ATTN_SMEM_FLOATS * 4)   // 229,024 B

__global__ __launch_bounds__(512, 1)
void k_attn(const float* __restrict__ rpe_table,
            const float* __restrict__ mask,
            const int*   __restrict__ rel) {
    extern __shared__ float sm[];
    float* qT = sm + OFF_QT;
    float* kT = sm + OFF_KT;
    float* vS = sm + OFF_V;
    float* QR = sm + OFF_QR;
    float* KR = sm + OFF_KR;
    float* Sb = sm + OFF_SB;
    unsigned char* srel = (unsigned char*)(sm + OFF_REL);

    int blk = blockIdx.x;
    int b = blk >> 2, h = blk & 3;
    int tid = threadIdx.x;
    const float scale = 0.17677669529663687f;  // 32^-0.5

    // rel_idx -> uint8 smem
    for (int e = tid; e < 4096; e += 512) srel[e] = (unsigned char)rel[e];

    // q (scaled, transposed), k (transposed), v (row-major)
    const float4* qkv4 = (const float4*)g_qkv;   // row pitch = 96 float4
#pragma unroll
    for (int it = 0; it < 4; ++it) {
        int e = it * 512 + tid;           // 2048 = 256 rows x 8 float4
        int i = e >> 3, c4 = e & 7;
        int base = (b * 256 + i) * 96;
        float4 qv = qkv4[base + h * 8 + c4];
        float4 kv = qkv4[base + 32 + h * 8 + c4];
        float4 vv = qkv4[base + 64 + h * 8 + c4];
        int c = c4 * 4;
        qT[(c + 0) * 260 + i] = qv.x * scale;
        qT[(c + 1) * 260 + i] = qv.y * scale;
        qT[(c + 2) * 260 + i] = qv.z * scale;
        qT[(c + 3) * 260 + i] = qv.w * scale;
        kT[(c + 0) * 260 + i] = kv.x;
        kT[(c + 1) * 260 + i] = kv.y;
        kT[(c + 2) * 260 + i] = kv.z;
        kT[(c + 3) * 260 + i] = kv.w;
        ((float4*)vS)[i * 8 + c4] = vv;
    }
    // per-head rpe slices
    for (int e = tid; e < NT * 96; e += 512) {
        int t = e / 96, c = e - t * 96;
        float v = rpe_table[t * 384 + h * 96 + c];
        if (c < 32)      QR[t * 33 + c]        = v * scale;    // q_rpe (scaled)
        else if (c < 64) KR[t * 33 + (c - 32)] = v;            // k_rpe
        else             (sm + OFF_VR)[t * 32 + (c - 64)] = v; // v_rpe
    }
    __syncthreads();

    // phase thread mappings
    int tr = tid >> 6, tc = tid & 63;     // scores: 4 rows x 4 cols per thread
    int li = tr * 4;
    int jr = tid >> 4, jlane = tid & 15;  // softmax: 32 rows, 16 lanes per row
    int w    = tid >> 5;                  // PV warp
    int lane = tid & 31;
    int g    = w >> 1;                    // 4-row group (0..7)
    int half = w & 1;                     // j-half
    int r_   = lane >> 3;                 // row within group (0..3)
    int c4   = lane & 7;                  // out col group

    const float4* qf   = (const float4*)qT;
    const float4* kf   = (const float4*)kT;
    const float4* vf   = (const float4*)vS;
    const float4* vrf  = (const float4*)(sm + OFF_VR);
    const float4* mask4 = (const float4*)mask;
    float4* Sb4 = (float4*)Sb;
    float4* Ob4 = (float4*)(sm + OFF_OB);
    float4* gc4 = (float4*)g_ctx;

    for (int ob = 0; ob < 8; ++ob) {
        // ---- scores: S = q·k + qr + kr + mask ----
        {
            int i0 = ob * 32 + li;            // global row (mult of 4)
            int I = i0 >> 2;                  // spatial row bin (== qT float4 col)
            int t = srel[I * 64 + tc];
            int tk = t * 33;
            // prefetch mask (global) before the FMA wall
            int mbase = b * 16384 + i0 * 64 + tc;
            float4 mv0 = mask4[mbase];
            float4 mv1 = mask4[mbase + 64];
            float4 mv2 = mask4[mbase + 128];
            float4 mv3 = mask4[mbase + 192];

            float4 z = make_float4(0.f, 0.f, 0.f, 0.f);
            float4 acc0 = z, acc1 = z, acc2 = z, acc3 = z, kr4 = z;
            float qr0 = 0.f, qr1 = 0.f, qr2 = 0.f, qr3 = 0.f;
#pragma unroll 8
            for (int k = 0; k < 32; ++k) {
                float4 a  = qf[k * 65 + I];
                float4 bb = kf[k * 65 + tc];
                float kv = KR[tk + k];
                float qv = QR[tk + k];
                axpy(a.x, bb, acc0); axpy(a.y, bb, acc1);
                axpy(a.z, bb, acc2); axpy(a.w, bb, acc3);
                qr0 = fmaf(a.x, kv, qr0); qr1 = fmaf(a.y, kv, qr1);
                qr2 = fmaf(a.z, kv, qr2); qr3 = fmaf(a.w, kv, qr3);
                axpy(qv, bb, kr4);
            }
            float4 s;
            s.x = acc0.x + qr0 + kr4.x + mv0.x;
            s.y = acc0.y + qr0 + kr4.y + mv0.y;
            s.z = acc0.z + qr0 + kr4.z + mv0.z;
            s.w = acc0.w + qr0 + kr4.w + mv0.w;
            Sb4[(li + 0) * 65 + tc] = s;
            s.x = acc1.x + qr1 + kr4.x + mv1.x;
            s.y = acc1.y + qr1 + kr4.y + mv1.y;
            s.z = acc1.z + qr1 + kr4.z + mv1.z;
            s.w = acc1.w + qr1 + kr4.w + mv1.w;
            Sb4[(li + 1) * 65 + tc] = s;
            s.x = acc2.x + qr2 + kr4.x + mv2.x;
            s.y = acc2.y + qr2 + kr4.y + mv2.y;
            s.z = acc2.z + qr2 + kr4.z + mv2.z;
            s.w = acc2.w + qr2 + kr4.w + mv2.w;
            Sb4[(li + 2) * 65 + tc] = s;
            s.x = acc3.x + qr3 + kr4.x + mv3.x;
            s.y = acc3.y + qr3 + kr4.y + mv3.y;
            s.z = acc3.z + qr3 + kr4.z + mv3.z;
            s.w = acc3.w + qr3 + kr4.w + mv3.w;
            Sb4[(li + 3) * 65 + tc] = s;
        }
        __syncthreads();

        // ---- softmax (full row; 16 lanes per row; 32 rows) — 2-pass smem ----
        {
            float* row = Sb + jr * 260;
            float mx = -3.0e38f;
#pragma unroll
            for (int s = 0; s < 16; ++s) mx = fmaxf(mx, row[jlane + 16 * s]);
#pragma unroll
            for (int o = 8; o > 0; o >>= 1) mx = fmaxf(mx, __shfl_xor_sync(0xffffffffu, mx, o));
            float sum = 0.f;
#pragma unroll
            for (int s = 0; s < 16; ++s) {
                float e = __expf(row[jlane + 16 * s] - mx);
                row[jlane + 16 * s] = e;
                sum += e;
            }
#pragma unroll
            for (int o = 8; o > 0; o >>= 1) sum += __shfl_xor_sync(0xffffffffu, sum, o);
            float inv = 1.0f / sum;
#pragma unroll
            for (int s = 0; s < 16; ++s) row[jlane + 16 * s] *= inv;
        }
        __syncthreads();

        // ---- PV + fused binned P*v_rpe ----
        // warp = (4-row group g, j-half), lane = (row r_, col c4).
        // All lanes in a warp share J each step -> v/vr loads broadcast:
        // 4x v = 4 phases, vr = 1, P = 1 (was ~16 phases with the old map).
        {
            int i = 4 * g + r_;                        // local row 0..31
            const float4* srow = Sb4 + i * 65;
            int I = ob * 8 + g;                        // spatial bin (same for group)
            const unsigned char* rrow = srel + I * 64;
            float4 acc = make_float4(0.f, 0.f, 0.f, 0.f);
            int J0 = half * 32;
#pragma unroll 4
            for (int J = J0; J < J0 + 32; ++J) {
                float4 p = srow[J];
                float4 v0 = vf[(4 * J + 0) * 8 + c4];
                float4 v1 = vf[(4 * J + 1) * 8 + c4];
                float4 v2 = vf[(4 * J + 2) * 8 + c4];
                float4 v3 = vf[(4 * J + 3) * 8 + c4];
                axpy(p.x, v0, acc);
                axpy(p.y, v1, acc);
                axpy(p.z, v2, acc);
                axpy(p.w, v3, acc);
                float pb = (p.x + p.y) + (p.z + p.w);
                float4 vr = vrf[rrow[J] * 8 + c4];
                axpy(pb, vr, acc);
            }
            if (half) Ob4[i * 8 + c4] = acc;
            __syncthreads();
            if (!half) {
                float4 c = Ob4[i * 8 + c4];
                acc.x += c.x; acc.y += c.y; acc.z += c.z; acc.w += c.w;
                gc4[(b * 256 + ob * 32 + i) * 32 + h * 8 + c4] = acc;
            }
        }
        __syncthreads();
    }
}

// ---------------- host ----------------
extern "C" void kernel_launch(void* const* d_in, const int* in_sizes, int n_in,
                              void* d_out, int out_size) {
    const float* x      = (const float*)d_in[0];
    const float* qkv_w  = (const float*)d_in[1];
    const float* qkv_b  = (const float*)d_in[2];
    const float* rpe    = (const float*)d_in[3];
    const float* proj_w = (const float*)d_in[4];
    const float* proj_b = (const float*)d_in[5];
    const float* mask   = (const float*)d_in[6];
    const int*   rel    = (const int*)d_in[7];
    float* out = (float*)d_out;

    float *p_qkv, *p_ctx, *p_wqkvT, *p_wprojT;
    cudaGetSymbolAddress((void**)&p_qkv,    g_qkv);
    cudaGetSymbolAddress((void**)&p_ctx,    g_ctx);
    cudaGetSymbolAddress((void**)&p_wqkvT,  g_wqkvT);
    cudaGetSymbolAddress((void**)&p_wprojT, g_wprojT);

    cudaFuncSetAttribute(k_gemm, cudaFuncAttributeMaxDynamicSharedMemorySize, GEMM_SMEM_BYTES);
    cudaFuncSetAttribute(k_attn, cudaFuncAttributeMaxDynamicSharedMemorySize, ATTN_SMEM_BYTES);

    // ncu alignment: k_attn at our launch index 3 (verified last round)
    k_transpose<<<192, 256>>>(qkv_w, proj_w);                                   // 0
    k_gemm<<<dim3(BB * LL / 64, 3), 256, GEMM_SMEM_BYTES>>>(x, p_wqkvT, qkv_b, p_qkv, 384); // 1
    k_dummy<<<1, 32>>>();                                                        // 2
    k_attn<<<BB * NHEAD, 512, ATTN_SMEM_BYTES>>>(rpe, mask, rel);                // 3
    k_gemm<<<dim3(BB * LL / 64, 1), 256, GEMM_SMEM_BYTES>>>(p_ctx, p_wprojT, proj_b, out, 128); // 4
}

// round 12
// speedup vs baseline: 1.2120x; 1.2120x over previous
#include <cuda_runtime.h>
#include <cuda_bf16.h>

// ---------------- problem constants ----------------
#define BB   128      // windows (= batch*nW)
#define LL   256      // tokens per window
#define NHEAD 4
#define HD   32
#define NT   225      // rpe table rows

// ---------------- scratch (static device globals) ----------------
__device__ float g_qkv[BB * LL * 384];      // [b][l][384]
__device__ float g_ctx[BB * LL * 128];      // [b][l][128]
__device__ float g_wqkvT[128 * 384];        // [k][n]
__device__ float g_wprojT[128 * 128];       // [k][n]

__device__ __forceinline__ void axpy(float a, const float4 b, float4& c) {
    c.x = fmaf(a, b.x, c.x); c.y = fmaf(a, b.y, c.y);
    c.z = fmaf(a, b.z, c.z); c.w = fmaf(a, b.w, c.w);
}

// ---------------- dummy (ncu launch-index alignment) ------------
__global__ void k_dummy() {}

// ---------------- kernel 0: transpose weights ----------------
__global__ void k_transpose(const float* __restrict__ wq, const float* __restrict__ wp) {
    int e = blockIdx.x * 256 + threadIdx.x;
    if (e < 384 * 128) { int n = e >> 7, k = e & 127; g_wqkvT[k * 384 + n] = wq[e]; }
    if (e < 128 * 128) { int n = e >> 7, k = e & 127; g_wprojT[k * 128 + n] = wp[e]; }
}

// ---------------- GEMM: C[p,n] = A[p,:128] @ Bt[:128,n] + bias[n] ----------
#define GEMM_SMEM_BYTES (64 * 132 * 4 + 128 * 32 * 16)
__global__ void k_gemm(const float* __restrict__ A, const float* __restrict__ Bt,
                       const float* __restrict__ bias, float* __restrict__ C, int N) {
    extern __shared__ float sm[];
    float*  xs = sm;                          // [64][132]
    float4* ws = (float4*)(sm + 64 * 132);    // [128][32] float4

    int p0 = blockIdx.x * 64, n0 = blockIdx.y * 128;
    int tid = threadIdx.x;

    const float4* A4 = (const float4*)A;
#pragma unroll
    for (int it = 0; it < 8; ++it) {
        int e = it * 256 + tid; int r = e >> 5, k4 = e & 31;
        float4 v = A4[(p0 + r) * 32 + k4];
        *(float4*)&xs[r * 132 + k4 * 4] = v;
    }
    const float4* B4 = (const float4*)Bt; int N4 = N >> 2;
#pragma unroll
    for (int it = 0; it < 16; ++it) {
        int e = it * 256 + tid; int k = e >> 5, n4 = e & 31;
        ws[k * 32 + n4] = B4[k * N4 + (n0 >> 2) + n4];
    }
    __syncthreads();

    int tx = tid & 15, ty = tid >> 4;
    int i0 = ty * 4, eo = ty & 1;
    int jA = 2 * tx + eo, jB = 2 * tx + (1 ^ eo);

    float4 z = make_float4(0.f, 0.f, 0.f, 0.f);
    float4 aA0 = z, aA1 = z, aA2 = z, aA3 = z;
    float4 aB0 = z, aB1 = z, aB2 = z, aB3 = z;

#pragma unroll 8
    for (int k = 0; k < 128; ++k) {
        float4 bA = ws[k * 32 + jA];
        float4 bB = ws[k * 32 + jB];
        float a0 = xs[(i0 + 0) * 132 + k];
        float a1 = xs[(i0 + 1) * 132 + k];
        float a2 = xs[(i0 + 2) * 132 + k];
        float a3 = xs[(i0 + 3) * 132 + k];
        axpy(a0, bA, aA0); axpy(a1, bA, aA1); axpy(a2, bA, aA2); axpy(a3, bA, aA3);
        axpy(a0, bB, aB0); axpy(a1, bB, aB1); axpy(a2, bB, aB2); axpy(a3, bB, aB3);
    }

    int nA = n0 + jA * 4, nB = n0 + jB * 4;
    float4 bsA = *(const float4*)&bias[nA];
    float4 bsB = *(const float4*)&bias[nB];
    float4 accA[4] = {aA0, aA1, aA2, aA3};
    float4 accB[4] = {aB0, aB1, aB2, aB3};
#pragma unroll
    for (int r = 0; r < 4; ++r) {
        int row = p0 + i0 + r;
        float4 oa = accA[r]; oa.x += bsA.x; oa.y += bsA.y; oa.z += bsA.z; oa.w += bsA.w;
        float4 ob = accB[r]; ob.x += bsB.x; ob.y += bsB.y; ob.z += bsB.z; ob.w += bsB.w;
        *(float4*)&C[row * N + nA] = oa;
        *(float4*)&C[row * N + nB] = ob;
    }
}

// ---------------- fused window attention: one CTA per (b, h), 512 threads ---
// smem offsets in floats:
#define OFF_QT   0        // qT[32][260]  (scaled, c-major)
#define OFF_KT   8320     // kT[32][260]
#define OFF_V    16640    // v[256][32]
#define OFF_QR   24832    // q_rpe*scale [225][33]
#define OFF_KR   32260    // k_rpe       [225][33]
#define OFF_VR   39688    // v_rpe       [225][32]
#define OFF_SB   46888    // score/prob buffer [32][260]
#define OFF_REL  55208    // uint8 rel_idx [64*64] = 1024 floats
#define ATTN_SMEM_FLOATS (OFF_REL + 1024)
#define ATTN_SMEM_BYTES  (ATTN_SMEM_FLOATS * 4)   // 224,928 B

__global__ __launch_bounds__(512, 1)
void k_attn(const float* __restrict__ rpe_table,
            const float* __restrict__ mask,
            const int*   __restrict__ rel) {
    extern __shared__ float sm[];
    float* qT = sm + OFF_QT;
    float* kT = sm + OFF_KT;
    float* vS = sm + OFF_V;
    float* QR = sm + OFF_QR;
    float* KR = sm + OFF_KR;
    float* Sb = sm + OFF_SB;
    unsigned char* srel = (unsigned char*)(sm + OFF_REL);

    int blk = blockIdx.x;
    int b = blk >> 2, h = blk & 3;
    int tid = threadIdx.x;
    const float scale = 0.17677669529663687f;  // 32^-0.5

    // rel_idx -> uint8 smem
    for (int e = tid; e < 4096; e += 512) srel[e] = (unsigned char)rel[e];

    // q (scaled, transposed), k (transposed), v (row-major)
    const float4* qkv4 = (const float4*)g_qkv;   // row pitch = 96 float4
#pragma unroll
    for (int it = 0; it < 4; ++it) {
        int e = it * 512 + tid;           // 2048 = 256 rows x 8 float4
        int i = e >> 3, c4 = e & 7;
        int base = (b * 256 + i) * 96;
        float4 qv = qkv4[base + h * 8 + c4];
        float4 kv = qkv4[base + 32 + h * 8 + c4];
        float4 vv = qkv4[base + 64 + h * 8 + c4];
        int c = c4 * 4;
        qT[(c + 0) * 260 + i] = qv.x * scale;
        qT[(c + 1) * 260 + i] = qv.y * scale;
        qT[(c + 2) * 260 + i] = qv.z * scale;
        qT[(c + 3) * 260 + i] = qv.w * scale;
        kT[(c + 0) * 260 + i] = kv.x;
        kT[(c + 1) * 260 + i] = kv.y;
        kT[(c + 2) * 260 + i] = kv.z;
        kT[(c + 3) * 260 + i] = kv.w;
        ((float4*)vS)[i * 8 + c4] = vv;
    }
    // per-head rpe slices
    for (int e = tid; e < NT * 96; e += 512) {
        int t = e / 96, c = e - t * 96;
        float v = rpe_table[t * 384 + h * 96 + c];
        if (c < 32)      QR[t * 33 + c]        = v * scale;    // q_rpe (scaled)
        else if (c < 64) KR[t * 33 + (c - 32)] = v;            // k_rpe
        else             (sm + OFF_VR)[t * 32 + (c - 64)] = v; // v_rpe
    }
    __syncthreads();

    // phase thread mappings
    int tr = tid >> 6, tc = tid & 63;     // scores: 4 rows x 4 cols per thread
    int li = tr * 4;
    int jr = tid >> 4, jlane = tid & 15;  // softmax: 32 rows, 16 lanes per row
    int w    = tid >> 5;                  // PV warp
    int lane = tid & 31;
    int g    = w & 7;                     // 4-row group (0..7), one rel bin
    int jh   = w >> 3;                    // j-half (0/1)
    int q4   = lane >> 3;                 // j-subquarter within half
    int c4   = lane & 7;                  // out col group

    const float4* qf   = (const float4*)qT;
    const float4* kf   = (const float4*)kT;
    const float4* vf   = (const float4*)vS;
    const float4* vrf  = (const float4*)(sm + OFF_VR);
    const float4* mask4 = (const float4*)mask;
    float4* Sb4 = (float4*)Sb;
    float4* gc4 = (float4*)g_ctx;

    for (int ob = 0; ob < 8; ++ob) {
        // ---- scores: S = q·k + qr + kr + mask ----
        {
            int i0 = ob * 32 + li;            // global row (mult of 4)
            int I = i0 >> 2;                  // spatial row bin (== qT float4 col)
            int t = srel[I * 64 + tc];
            int tk = t * 33;
            // prefetch mask (global) before the FMA wall
            int mbase = b * 16384 + i0 * 64 + tc;
            float4 mv0 = mask4[mbase];
            float4 mv1 = mask4[mbase + 64];
            float4 mv2 = mask4[mbase + 128];
            float4 mv3 = mask4[mbase + 192];

            float4 z = make_float4(0.f, 0.f, 0.f, 0.f);
            float4 acc0 = z, acc1 = z, acc2 = z, acc3 = z, kr4 = z;
            float qr0 = 0.f, qr1 = 0.f, qr2 = 0.f, qr3 = 0.f;
#pragma unroll 8
            for (int k = 0; k < 32; ++k) {
                float4 a  = qf[k * 65 + I];
                float4 bb = kf[k * 65 + tc];
                float kv = KR[tk + k];
                float qv = QR[tk + k];
                axpy(a.x, bb, acc0); axpy(a.y, bb, acc1);
                axpy(a.z, bb, acc2); axpy(a.w, bb, acc3);
                qr0 = fmaf(a.x, kv, qr0); qr1 = fmaf(a.y, kv, qr1);
                qr2 = fmaf(a.z, kv, qr2); qr3 = fmaf(a.w, kv, qr3);
                axpy(qv, bb, kr4);
            }
            float4 s;
            s.x = acc0.x + qr0 + kr4.x + mv0.x;
            s.y = acc0.y + qr0 + kr4.y + mv0.y;
            s.z = acc0.z + qr0 + kr4.z + mv0.z;
            s.w = acc0.w + qr0 + kr4.w + mv0.w;
            Sb4[(li + 0) * 65 + tc] = s;
            s.x = acc1.x + qr1 + kr4.x + mv1.x;
            s.y = acc1.y + qr1 + kr4.y + mv1.y;
            s.z = acc1.z + qr1 + kr4.z + mv1.z;
            s.w = acc1.w + qr1 + kr4.w + mv1.w;
            Sb4[(li + 1) * 65 + tc] = s;
            s.x = acc2.x + qr2 + kr4.x + mv2.x;
            s.y = acc2.y + qr2 + kr4.y + mv2.y;
            s.z = acc2.z + qr2 + kr4.z + mv2.z;
            s.w = acc2.w + qr2 + kr4.w + mv2.w;
            Sb4[(li + 2) * 65 + tc] = s;
            s.x = acc3.x + qr3 + kr4.x + mv3.x;
            s.y = acc3.y + qr3 + kr4.y + mv3.y;
            s.z = acc3.z + qr3 + kr4.z + mv3.z;
            s.w = acc3.w + qr3 + kr4.w + mv3.w;
            Sb4[(li + 3) * 65 + tc] = s;
        }
        __syncthreads();

        // ---- softmax (full row; 16 lanes per row; 32 rows) — 2-pass smem ----
        {
            float* row = Sb + jr * 260;
            float mx = -3.0e38f;
#pragma unroll
            for (int s = 0; s < 16; ++s) mx = fmaxf(mx, row[jlane + 16 * s]);
#pragma unroll
            for (int o = 8; o > 0; o >>= 1) mx = fmaxf(mx, __shfl_xor_sync(0xffffffffu, mx, o));
            float sum = 0.f;
#pragma unroll
            for (int s = 0; s < 16; ++s) {
                float e = __expf(row[jlane + 16 * s] - mx);
                row[jlane + 16 * s] = e;
                sum += e;
            }
#pragma unroll
            for (int o = 8; o > 0; o >>= 1) sum += __shfl_xor_sync(0xffffffffu, sum, o);
            float inv = 1.0f / sum;
#pragma unroll
            for (int s = 0; s < 16; ++s) row[jlane + 16 * s] *= inv;
        }
        __syncthreads();

        // ---- PV + fused binned P*v_rpe ----
        // warp = (row-group g of 4 rows [one rel bin], j-half jh);
        // lane = (q4 = j-subquarter, c4 = col group); thread = 4 rows x 8 J.
        // v/vr loads amortized over 4 rows: 9 LDS + 20 axpy per J.
        {
            const float4* s0 = Sb4 + (4 * g + 0) * 65;
            const float4* s1 = Sb4 + (4 * g + 1) * 65;
            const float4* s2 = Sb4 + (4 * g + 2) * 65;
            const float4* s3 = Sb4 + (4 * g + 3) * 65;
            int I = ob * 8 + g;
            const unsigned char* rrow = srel + I * 64;
            float4 a0 = make_float4(0.f, 0.f, 0.f, 0.f);
            float4 a1 = a0, a2 = a0, a3 = a0;
            int Jbase = jh * 32 + q4 * 8;
#pragma unroll
            for (int jj = 0; jj < 8; ++jj) {
                int J = Jbase + jj;
                float4 p0 = s0[J];
                float4 p1 = s1[J];
                float4 p2 = s2[J];
                float4 p3 = s3[J];
                float4 v0 = vf[(4 * J + 0) * 8 + c4];
                float4 v1 = vf[(4 * J + 1) * 8 + c4];
                float4 v2 = vf[(4 * J + 2) * 8 + c4];
                float4 v3 = vf[(4 * J + 3) * 8 + c4];
                axpy(p0.x, v0, a0); axpy(p0.y, v1, a0); axpy(p0.z, v2, a0); axpy(p0.w, v3, a0);
                axpy(p1.x, v0, a1); axpy(p1.y, v1, a1); axpy(p1.z, v2, a1); axpy(p1.w, v3, a1);
                axpy(p2.x, v0, a2); axpy(p2.y, v1, a2); axpy(p2.z, v2, a2); axpy(p2.w, v3, a2);
                axpy(p3.x, v0, a3); axpy(p3.y, v1, a3); axpy(p3.z, v2, a3); axpy(p3.w, v3, a3);
                float4 vr = vrf[rrow[J] * 8 + c4];
                axpy((p0.x + p0.y) + (p0.z + p0.w), vr, a0);
                axpy((p1.x + p1.y) + (p1.z + p1.w), vr, a1);
                axpy((p2.x + p2.y) + (p2.z + p2.w), vr, a2);
                axpy((p3.x + p3.y) + (p3.z + p3.w), vr, a3);
            }
            // reduce over q4 (lane bits 3,4)
#pragma unroll
            for (int o = 8; o <= 16; o <<= 1) {
                a0.x += __shfl_xor_sync(0xffffffffu, a0.x, o);
                a0.y += __shfl_xor_sync(0xffffffffu, a0.y, o);
                a0.z += __shfl_xor_sync(0xffffffffu, a0.z, o);
                a0.w += __shfl_xor_sync(0xffffffffu, a0.w, o);
                a1.x += __shfl_xor_sync(0xffffffffu, a1.x, o);
                a1.y += __shfl_xor_sync(0xffffffffu, a1.y, o);
                a1.z += __shfl_xor_sync(0xffffffffu, a1.z, o);
                a1.w += __shfl_xor_sync(0xffffffffu, a1.w, o);
                a2.x += __shfl_xor_sync(0xffffffffu, a2.x, o);
                a2.y += __shfl_xor_sync(0xffffffffu, a2.y, o);
                a2.z += __shfl_xor_sync(0xffffffffu, a2.z, o);
                a2.w += __shfl_xor_sync(0xffffffffu, a2.w, o);
                a3.x += __shfl_xor_sync(0xffffffffu, a3.x, o);
                a3.y += __shfl_xor_sync(0xffffffffu, a3.y, o);
                a3.z += __shfl_xor_sync(0xffffffffu, a3.z, o);
                a3.w += __shfl_xor_sync(0xffffffffu, a3.w, o);
            }
            // cross-half combine via Sb[0..255] scratch AFTER all P reads retire
            __syncthreads();
            if (jh == 1 && q4 == 0) {
                Sb4[(4 * g + 0) * 8 + c4] = a0;
                Sb4[(4 * g + 1) * 8 + c4] = a1;
                Sb4[(4 * g + 2) * 8 + c4] = a2;
                Sb4[(4 * g + 3) * 8 + c4] = a3;
            }
            __syncthreads();
            if (jh == 0 && q4 == 0) {
                int row0 = b * 256 + ob * 32 + 4 * g;
                float4 c0 = Sb4[(4 * g + 0) * 8 + c4];
                float4 c1 = Sb4[(4 * g + 1) * 8 + c4];
                float4 c2 = Sb4[(4 * g + 2) * 8 + c4];
                float4 c3 = Sb4[(4 * g + 3) * 8 + c4];
                a0.x += c0.x; a0.y += c0.y; a0.z += c0.z; a0.w += c0.w;
                a1.x += c1.x; a1.y += c1.y; a1.z += c1.z; a1.w += c1.w;
                a2.x += c2.x; a2.y += c2.y; a2.z += c2.z; a2.w += c2.w;
                a3.x += c3.x; a3.y += c3.y; a3.z += c3.z; a3.w += c3.w;
                gc4[(row0 + 0) * 32 + h * 8 + c4] = a0;
                gc4[(row0 + 1) * 32 + h * 8 + c4] = a1;
                gc4[(row0 + 2) * 32 + h * 8 + c4] = a2;
                gc4[(row0 + 3) * 32 + h * 8 + c4] = a3;
            }
        }
        __syncthreads();
    }
}

// ---------------- host ----------------
extern "C" void kernel_launch(void* const* d_in, const int* in_sizes, int n_in,
                              void* d_out, int out_size) {
    const float* x      = (const float*)d_in[0];
    const float* qkv_w  = (const float*)d_in[1];
    const float* qkv_b  = (const float*)d_in[2];
    const float* rpe    = (const float*)d_in[3];
    const float* proj_w = (const float*)d_in[4];
    const float* proj_b = (const float*)d_in[5];
    const float* mask   = (const float*)d_in[6];
    const int*   rel    = (const int*)d_in[7];
    float* out = (float*)d_out;

    float *p_qkv, *p_ctx, *p_wqkvT, *p_wprojT;
    cudaGetSymbolAddress((void**)&p_qkv,    g_qkv);
    cudaGetSymbolAddress((void**)&p_ctx,    g_ctx);
    cudaGetSymbolAddress((void**)&p_wqkvT,  g_wqkvT);
    cudaGetSymbolAddress((void**)&p_wprojT, g_wprojT);

    cudaFuncSetAttribute(k_gemm, cudaFuncAttributeMaxDynamicSharedMemorySize, GEMM_SMEM_BYTES);
    cudaFuncSetAttribute(k_attn, cudaFuncAttributeMaxDynamicSharedMemorySize, ATTN_SMEM_BYTES);

    // ncu alignment: k_attn at our launch index 3
    k_transpose<<<192, 256>>>(qkv_w, proj_w);                                   // 0
    k_gemm<<<dim3(BB * LL / 64, 3), 256, GEMM_SMEM_BYTES>>>(x, p_wqkvT, qkv_b, p_qkv, 384); // 1
    k_dummy<<<1, 32>>>();                                                        // 2
    k_attn<<<BB * NHEAD, 512, ATTN_SMEM_BYTES>>>(rpe, mask, rel);                // 3
    k_gemm<<<dim3(BB * LL / 64, 1), 256, GEMM_SMEM_BYTES>>>(p_ctx, p_wprojT, proj_b, out, 128); // 4
}